// round 16
// baseline (speedup 1.0000x reference)
#include <cuda_runtime.h>
#include <math.h>

// Problem dims
#define HH 256
#define QQ 64
#define DD 512
#define VV 34
#define LL 1024
#define NN 64
#define TT 256
#define NB 128   // decode grid blocks (must be <= SM count for residency)

// ---------------- device scratch ----------------
__device__ float g_hid[65536 * 512];          // hidden of k/v MLPs (reused)
__device__ float g_key[NN * QQ * LL];         // keyT: [n][q][l]
__device__ float g_value[NN * LL * HH];       // [n][l][h]
__device__ float g_W0T[768 * 1024];           // [k][remapped gate-col]
__device__ float g_W1T[512 * 1024];
__device__ float g_W2T[512 * 1024];
__device__ float g_kW0T[512 * 512];
__device__ float g_kW1T[512 * 64];
__device__ float g_vW0T[512 * 256];
__device__ float g_vW1T[256 * 256];
__device__ float g_qW0T[256 * 256];
__device__ float g_qW1T[256 * 64];
__device__ float g_h[2 * 3 * NN * HH];        // parity-double-buffered h
__device__ float g_c[2 * 3 * NN * HH];
__device__ float g_ctx[NN * HH];

// grid barrier state (cumulative count; reset by init_state each launch)
__device__ unsigned g_bcnt;
__device__ unsigned g_bgen;

__device__ __forceinline__ void gridbar(unsigned& lg)
{
    __syncthreads();
    if (threadIdx.x == 0) {
        __threadfence();
        unsigned arr = atomicAdd(&g_bcnt, 1u);
        if (arr == (unsigned)NB * (lg + 1u) - 1u) {
            atomicExch(&g_bgen, lg + 1u);
        } else {
            while (*((volatile unsigned*)&g_bgen) <= lg) __nanosleep(40);
        }
        __threadfence();
    }
    lg++;
    __syncthreads();
}

// ---------------- transpose: WT[(rowOff+c)*ldT + perm(r)] = W[r*C + c] ----------------
// remap=1: r = g*256+m  ->  (m>>1)*8 + g*2 + (m&1)   (block-contiguous gate cols)
__global__ void transpose_into(const float* __restrict__ W, float* __restrict__ WT,
                               int R, int C, int rowOff, int ldT, int remap)
{
    __shared__ float tile[32][33];
    int c0 = blockIdx.x * 32, r0 = blockIdx.y * 32;
    for (int i = threadIdx.y; i < 32; i += 8) {
        int r = r0 + i, c = c0 + threadIdx.x;
        if (r < R && c < C) tile[i][threadIdx.x] = W[(size_t)r * C + c];
    }
    __syncthreads();
    for (int i = threadIdx.y; i < 32; i += 8) {
        int c = c0 + i, r = r0 + threadIdx.x;
        if (r < R && c < C) {
            int rr = r;
            if (remap) rr = ((r & 255) >> 1) * 8 + ((r >> 8) << 1) + (r & 1);
            WT[(size_t)(rowOff + c) * ldT + rr] = tile[threadIdx.x][i];
        }
    }
}

// ---------------- init h/c state + reset grid barrier ----------------
__global__ void init_state(const float* __restrict__ inith, const float* __restrict__ initc,
                           float* __restrict__ h0, float* __restrict__ c0)
{
    if (blockIdx.x == 0 && threadIdx.x == 0) { g_bcnt = 0u; g_bgen = 0u; }
    int idx = blockIdx.x * 256 + threadIdx.x;   // 3*64*256 = 49152
    int i = idx >> 14;                          // layer
    int k = idx & 255;
    h0[idx] = inith[i * 256 + k];
    c0[idx] = initc[i * 256 + k];
}

// ---------------- big GEMM: C = act(A[M,K] @ B[K,N] + bias) ----------------
// tstore: 0 linear; 1: row r->(n=r&63,l=r>>6), idx=((n<<10)+l)*N+col (value layout)
//         2: keyT layout idx = n*65536 + col*1024 + l
__global__ __launch_bounds__(256) void gemm_kernel(
    const float* __restrict__ A, const float* __restrict__ B,
    const float* __restrict__ bias, float* __restrict__ C,
    int M, int N, int K, int act, int tstore)
{
    __shared__ float As[16][64];
    __shared__ float Bs[16][64];
    int t = threadIdx.x;
    int m0 = blockIdx.y << 6, n0 = blockIdx.x << 6;
    int am = t >> 2, ak = (t & 3) << 2;
    int bk = t >> 4, bn = (t & 15) << 2;
    int ty = t >> 4, tx = t & 15;
    float acc[4][4] = {};
    const float* Ap = A + (size_t)(m0 + am) * K + ak;
    const float* Bp = B + (size_t)bk * N + n0 + bn;
    for (int kc = 0; kc < K; kc += 16) {
        float4 av = *(const float4*)(Ap + kc);
        As[ak + 0][am] = av.x; As[ak + 1][am] = av.y;
        As[ak + 2][am] = av.z; As[ak + 3][am] = av.w;
        *(float4*)&Bs[bk][bn] = *(const float4*)(Bp + (size_t)kc * N);
        __syncthreads();
#pragma unroll
        for (int k = 0; k < 16; ++k) {
            float4 a4 = ((const float4*)As[k])[ty];
            float4 b4 = ((const float4*)Bs[k])[tx];
            acc[0][0] += a4.x * b4.x; acc[0][1] += a4.x * b4.y;
            acc[0][2] += a4.x * b4.z; acc[0][3] += a4.x * b4.w;
            acc[1][0] += a4.y * b4.x; acc[1][1] += a4.y * b4.y;
            acc[1][2] += a4.y * b4.z; acc[1][3] += a4.y * b4.w;
            acc[2][0] += a4.z * b4.x; acc[2][1] += a4.z * b4.y;
            acc[2][2] += a4.z * b4.z; acc[2][3] += a4.z * b4.w;
            acc[3][0] += a4.w * b4.x; acc[3][1] += a4.w * b4.y;
            acc[3][2] += a4.w * b4.z; acc[3][3] += a4.w * b4.w;
        }
        __syncthreads();
    }
#pragma unroll
    for (int i = 0; i < 4; ++i) {
        int r = m0 + ty * 4 + i;
#pragma unroll
        for (int j = 0; j < 4; ++j) {
            int col = n0 + tx * 4 + j;
            float v = acc[i][j] + bias[col];
            if (act) v = v > 0.f ? v : expm1f(v);
            size_t idx;
            if (tstore == 1) {
                int nn = r & 63, l = r >> 6;
                idx = (size_t)((nn << 10) + l) * N + col;
            } else if (tstore == 2) {
                int nn = r & 63, l = r >> 6;
                idx = ((size_t)nn << 16) + ((size_t)col << 10) + l;
            } else {
                idx = (size_t)r * N + col;
            }
            C[idx] = v;
        }
    }
}

// ---------------- persistent decode kernel ----------------
struct SmLstm {
    float As[32][64];
    float Bs2[8][32];
    float gsm[64][9];
};
struct SmAttn {
    float h2s[256];
    float hid[256];
    float qv[64];
    float sc[1024];
    float red[32];
    float4 part4[256];
    float ctxs[256];
};
union SmU { SmLstm l; SmAttn a; };

// one LSTM layer phase. Block b owns m in {2b, 2b+1}, all 4 gates (8 gate cols).
__device__ __forceinline__ void lstm_phase(
    SmLstm& s, int b, int t,
    const float* __restrict__ WT, int K,
    const float* __restrict__ bih, const float* __restrict__ bhh,
    const float* __restrict__ s0, const float* __restrict__ s1,
    const float* __restrict__ s2,
    const int* __restrict__ lab, const float* __restrict__ emb,
    const float* __restrict__ cprev, float* __restrict__ cnew,
    float* __restrict__ hnew)
{
    int m0 = b << 1;
    int n = t & 63, gp = t >> 6;          // thread computes gates (gp, m0) & (gp, m0+1)
    float acc0 = 0.f, acc1 = 0.f;
    int an = t >> 2, ak = (t & 3) << 2;
    int bkk = t >> 3, bc = t & 7;

    for (int kc = 0; kc < K; kc += 32) {
        // stage xin chunk (32k x 64n): each thread loads 2 float4 of its row
        int kg = kc + ak;
        int seg = kg >> 8, kk = kg & 255;
        const float* src = (seg == 0) ? (s0 + an * 256)
                         : (seg == 1) ? (lab ? (emb + lab[an] * 256) : (s1 + an * 256))
                                      : (s2 + an * 256);
        float4 v = *(const float4*)(src + kk);
        float4 v2 = *(const float4*)(src + kk + 16);
        s.As[ak + 0][an] = v.x;  s.As[ak + 1][an] = v.y;
        s.As[ak + 2][an] = v.z;  s.As[ak + 3][an] = v.w;
        s.As[ak + 16][an] = v2.x; s.As[ak + 17][an] = v2.y;
        s.As[ak + 18][an] = v2.z; s.As[ak + 19][an] = v2.w;
        // stage weights (32k x 8 cols), block-contiguous remapped layout
        s.Bs2[bc][bkk] = WT[(size_t)(kc + bkk) * 1024 + (b << 3) + bc];
        __syncthreads();
#pragma unroll
        for (int k = 0; k < 32; k += 4) {
            float4 w0 = *(const float4*)&s.Bs2[gp * 2 + 0][k];
            float4 w1 = *(const float4*)&s.Bs2[gp * 2 + 1][k];
            float a0 = s.As[k + 0][n], a1 = s.As[k + 1][n];
            float a2 = s.As[k + 2][n], a3 = s.As[k + 3][n];
            acc0 += a0 * w0.x; acc1 += a0 * w1.x;
            acc0 += a1 * w0.y; acc1 += a1 * w1.y;
            acc0 += a2 * w0.z; acc1 += a2 * w1.z;
            acc0 += a3 * w0.w; acc1 += a3 * w1.w;
        }
        __syncthreads();
    }
    int col0 = gp * 256 + m0, col1 = col0 + 1;
    s.gsm[n][gp * 2 + 0] = acc0 + bih[col0] + bhh[col0];
    s.gsm[n][gp * 2 + 1] = acc1 + bih[col1] + bhh[col1];
    __syncthreads();
    if (t < 128) {
        int nn = t >> 1, mm = t & 1;
        float i_ = s.gsm[nn][0 + mm];
        float f_ = s.gsm[nn][2 + mm];
        float g_ = s.gsm[nn][4 + mm];
        float o_ = s.gsm[nn][6 + mm];
        i_ = 1.f / (1.f + expf(-i_));
        f_ = 1.f / (1.f + expf(-f_));
        o_ = 1.f / (1.f + expf(-o_));
        int mg = m0 + mm;
        float c = f_ * cprev[nn * 256 + mg] + i_ * tanhf(g_);
        cnew[nn * 256 + mg] = c;
        hnew[nn * 256 + mg] = o_ * tanhf(c);
    }
}

// attention phase: blocks 0..63 (one per batch row). keyT layout [n][q][l].
__device__ __forceinline__ void attn_phase(
    SmAttn& s, int n, int t,
    const float* __restrict__ h2buf, const int* __restrict__ seq_lens,
    const float* __restrict__ keyT, const float* __restrict__ value,
    const float* __restrict__ qW0T, const float* __restrict__ qb0,
    const float* __restrict__ qW1T, const float* __restrict__ qb1,
    const float* __restrict__ outW, const float* __restrict__ outb,
    float* __restrict__ ctx_out, float* __restrict__ outs, int tstep)
{
    int w = t >> 5, lane = t & 31;
    int len = seq_lens[n];

    // q = MLP(h2)
    s.h2s[t] = h2buf[n * 256 + t];
    __syncthreads();
    {
        float a = qb0[t];
        const float* wp = qW0T + t;
#pragma unroll 8
        for (int k = 0; k < 256; ++k) a += wp[k * 256] * s.h2s[k];
        s.hid[t] = a > 0.f ? a : expm1f(a);
    }
    __syncthreads();
    if (t < 64) {
        float a = qb1[t];
        const float* wp = qW1T + t;
#pragma unroll 8
        for (int k = 0; k < 256; ++k) a += wp[k * 64] * s.hid[k];
        s.qv[t] = a;
    }
    __syncthreads();

    // scores: thread per l, coalesced over keyT rows
    {
        const float* kb = keyT + ((size_t)n << 16);
#pragma unroll
        for (int l0 = 0; l0 < 1024; l0 += 256) {
            int l = l0 + t;
            if (l < len) {
                float acc = 0.f;
                const float* kp = kb + l;
#pragma unroll
                for (int q = 0; q < 64; ++q) acc += kp[(size_t)q << 10] * s.qv[q];
                s.sc[l] = acc;
            }
        }
    }
    __syncthreads();

    // masked softmax
    float mval = -1e30f;
    for (int l = t; l < 1024; l += 256)
        if (l < len) mval = fmaxf(mval, s.sc[l]);
#pragma unroll
    for (int o = 16; o; o >>= 1) mval = fmaxf(mval, __shfl_xor_sync(0xffffffffu, mval, o));
    if (lane == 0) s.red[w] = mval;
    __syncthreads();
    if (t == 0) {
        float mm = s.red[0];
        for (int i = 1; i < 8; ++i) mm = fmaxf(mm, s.red[i]);
        s.red[8] = mm;
    }
    __syncthreads();
    float M = s.red[8];
    float sum = 0.f;
    for (int l = t; l < 1024; l += 256) {
        float e = (l < len) ? expf(s.sc[l] - M) : 0.f;
        s.sc[l] = e;
        sum += e;
    }
#pragma unroll
    for (int o = 16; o; o >>= 1) sum += __shfl_xor_sync(0xffffffffu, sum, o);
    if (lane == 0) s.red[16 + w] = sum;
    __syncthreads();
    if (t == 0) {
        float ss = 0.f;
        for (int i = 0; i < 8; ++i) ss += s.red[16 + i];
        s.red[9] = 1.f / ss;
    }
    __syncthreads();
    float inv = s.red[9];

    // ctx = a @ value   (value layout [n][l][h])
    {
        int hv = t & 63, lc = t >> 6;
        int l0 = lc << 8;
        int l1 = min(l0 + 256, len);
        float4 a4 = make_float4(0.f, 0.f, 0.f, 0.f);
        const float* vb = value + ((size_t)(n << 10)) * 256 + (hv << 2);
#pragma unroll 4
        for (int l = l0; l < l1; ++l) {
            float a = s.sc[l];
            float4 v4 = *(const float4*)(vb + ((size_t)l << 8));
            a4.x += a * v4.x; a4.y += a * v4.y;
            a4.z += a * v4.z; a4.w += a * v4.w;
        }
        s.part4[t] = a4;
    }
    __syncthreads();
    if (t < 64) {
        float4 r = s.part4[t], b1 = s.part4[t + 64], b2 = s.part4[t + 128], b3 = s.part4[t + 192];
        r.x = (r.x + b1.x + b2.x + b3.x) * inv;
        r.y = (r.y + b1.y + b2.y + b3.y) * inv;
        r.z = (r.z + b1.z + b2.z + b3.z) * inv;
        r.w = (r.w + b1.w + b2.w + b3.w) * inv;
        s.ctxs[t * 4 + 0] = r.x; s.ctxs[t * 4 + 1] = r.y;
        s.ctxs[t * 4 + 2] = r.z; s.ctxs[t * 4 + 3] = r.w;
        *(float4*)(ctx_out + n * 256 + t * 4) = r;
    }
    __syncthreads();

    // out = [ctx, h2] @ outW^T + outb
    if (tstep >= 0) {
        for (int v = w; v < 34; v += 8) {
            const float* wr = outW + v * 512;
            float a = 0.f;
            for (int k = lane; k < 512; k += 32) {
                float x = (k < 256) ? s.ctxs[k] : s.h2s[k - 256];
                a += x * wr[k];
            }
#pragma unroll
            for (int o = 16; o; o >>= 1) a += __shfl_xor_sync(0xffffffffu, a, o);
            if (lane == 0)
                outs[((size_t)tstep * 64 + n) * 34 + v] = a + outb[v];
        }
    }
}

__global__ __launch_bounds__(256) void decode_kernel(
    const int* __restrict__ seq_lens, const int* __restrict__ labels,
    const float* __restrict__ emb,
    const float* __restrict__ W0T, const float* __restrict__ W1T,
    const float* __restrict__ W2T,
    const float* __restrict__ bih0, const float* __restrict__ bhh0,
    const float* __restrict__ bih1, const float* __restrict__ bhh1,
    const float* __restrict__ bih2, const float* __restrict__ bhh2,
    const float* __restrict__ qW0T, const float* __restrict__ qb0,
    const float* __restrict__ qW1T, const float* __restrict__ qb1,
    const float* __restrict__ outW, const float* __restrict__ outb,
    const float* __restrict__ keyT, const float* __restrict__ value,
    float* __restrict__ hb, float* __restrict__ cb,
    float* __restrict__ ctx, float* __restrict__ outs)
{
    __shared__ SmU sm;
    unsigned lg = 0;
    int b = blockIdx.x, t = threadIdx.x;
    const int NS = NN * HH;   // 16384

    // initial ctx from h_init (parity 0)
    if (b < 64)
        attn_phase(sm.a, b, t, hb + 2 * NS, seq_lens, keyT, value,
                   qW0T, qb0, qW1T, qb1, outW, outb, ctx, outs, -1);
    gridbar(lg);

    for (int st = 0; st < TT; ++st) {
        int p = st & 1, q = p ^ 1;
        float* hp = hb + (size_t)p * 3 * NS;
        float* hq = hb + (size_t)q * 3 * NS;
        float* cp = cb + (size_t)p * 3 * NS;
        float* cq = cb + (size_t)q * 3 * NS;

        lstm_phase(sm.l, b, t, W0T, 768, bih0, bhh0,
                   ctx, (const float*)0, hp + 0 * NS,
                   labels + st * 64, emb,
                   cp + 0 * NS, cq + 0 * NS, hq + 0 * NS);
        gridbar(lg);
        lstm_phase(sm.l, b, t, W1T, 512, bih1, bhh1,
                   hq + 0 * NS, hp + 1 * NS, (const float*)0,
                   (const int*)0, (const float*)0,
                   cp + 1 * NS, cq + 1 * NS, hq + 1 * NS);
        gridbar(lg);
        lstm_phase(sm.l, b, t, W2T, 512, bih2, bhh2,
                   hq + 1 * NS, hp + 2 * NS, (const float*)0,
                   (const int*)0, (const float*)0,
                   cp + 2 * NS, cq + 2 * NS, hq + 2 * NS);
        gridbar(lg);
        if (b < 64)
            attn_phase(sm.a, b, t, hq + 2 * NS, seq_lens, keyT, value,
                       qW0T, qb0, qW1T, qb1, outW, outb, ctx, outs, st);
        gridbar(lg);
    }
}

// ---------------- host ----------------
extern "C" void kernel_launch(void* const* d_in, const int* in_sizes, int n_in,
                              void* d_out, int out_size)
{
    const float* seqs     = (const float*)d_in[0];
    const int*   seq_lens = (const int*)  d_in[1];
    const int*   labels   = (const int*)  d_in[2];
    const float* emb      = (const float*)d_in[3];
    const float* inith    = (const float*)d_in[4];
    const float* initc    = (const float*)d_in[5];
    const float* Wih0 = (const float*)d_in[6],  *Whh0 = (const float*)d_in[7];
    const float* bih0 = (const float*)d_in[8],  *bhh0 = (const float*)d_in[9];
    const float* Wih1 = (const float*)d_in[10], *Whh1 = (const float*)d_in[11];
    const float* bih1 = (const float*)d_in[12], *bhh1 = (const float*)d_in[13];
    const float* Wih2 = (const float*)d_in[14], *Whh2 = (const float*)d_in[15];
    const float* bih2 = (const float*)d_in[16], *bhh2 = (const float*)d_in[17];
    const float* qW0 = (const float*)d_in[18], *qb0 = (const float*)d_in[19];
    const float* qW1 = (const float*)d_in[20], *qb1 = (const float*)d_in[21];
    const float* kW0 = (const float*)d_in[22], *kb0 = (const float*)d_in[23];
    const float* kW1 = (const float*)d_in[24], *kb1 = (const float*)d_in[25];
    const float* vW0 = (const float*)d_in[26], *vb0 = (const float*)d_in[27];
    const float* vW1 = (const float*)d_in[28], *vb1 = (const float*)d_in[29];
    const float* outW = (const float*)d_in[30], *outb = (const float*)d_in[31];
    float* outs = (float*)d_out;

    float *hid, *key, *val, *W0T, *W1T, *W2T;
    float *kW0T, *kW1T, *vW0T, *vW1T, *qW0T, *qW1T;
    float *hb, *cb, *ctx;
    cudaGetSymbolAddress((void**)&hid,  g_hid);
    cudaGetSymbolAddress((void**)&key,  g_key);
    cudaGetSymbolAddress((void**)&val,  g_value);
    cudaGetSymbolAddress((void**)&W0T,  g_W0T);
    cudaGetSymbolAddress((void**)&W1T,  g_W1T);
    cudaGetSymbolAddress((void**)&W2T,  g_W2T);
    cudaGetSymbolAddress((void**)&kW0T, g_kW0T);
    cudaGetSymbolAddress((void**)&kW1T, g_kW1T);
    cudaGetSymbolAddress((void**)&vW0T, g_vW0T);
    cudaGetSymbolAddress((void**)&vW1T, g_vW1T);
    cudaGetSymbolAddress((void**)&qW0T, g_qW0T);
    cudaGetSymbolAddress((void**)&qW1T, g_qW1T);
    cudaGetSymbolAddress((void**)&hb,   g_h);
    cudaGetSymbolAddress((void**)&cb,   g_c);
    cudaGetSymbolAddress((void**)&ctx,  g_ctx);

    auto tr = [&](const float* W, float* WT, int R, int C, int ro, int ld, int rm) {
        dim3 g((C + 31) / 32, (R + 31) / 32), bl(32, 8);
        transpose_into<<<g, bl>>>(W, WT, R, C, ro, ld, rm);
    };
    // LSTM weights: remapped block-contiguous gate columns
    tr(Wih0, W0T, 1024, 512, 0, 1024, 1);
    tr(Whh0, W0T, 1024, 256, 512, 1024, 1);
    tr(Wih1, W1T, 1024, 256, 0, 1024, 1);
    tr(Whh1, W1T, 1024, 256, 256, 1024, 1);
    tr(Wih2, W2T, 1024, 256, 0, 1024, 1);
    tr(Whh2, W2T, 1024, 256, 256, 1024, 1);
    tr(kW0, kW0T, 512, 512, 0, 512, 0);
    tr(kW1, kW1T, 64, 512, 0, 64, 0);
    tr(vW0, vW0T, 256, 512, 0, 256, 0);
    tr(vW1, vW1T, 256, 256, 0, 256, 0);
    tr(qW0, qW0T, 256, 256, 0, 256, 0);
    tr(qW1, qW1T, 64, 256, 0, 64, 0);

    // key / value precompute (key stored transposed [n][q][l])
    gemm_kernel<<<dim3(8, 1024), 256>>>(seqs, kW0T, kb0, hid, 65536, 512, 512, 1, 0);
    gemm_kernel<<<dim3(1, 1024), 256>>>(hid, kW1T, kb1, key, 65536, 64, 512, 0, 2);
    gemm_kernel<<<dim3(4, 1024), 256>>>(seqs, vW0T, vb0, hid, 65536, 256, 512, 1, 0);
    gemm_kernel<<<dim3(4, 1024), 256>>>(hid, vW1T, vb1, val, 65536, 256, 256, 0, 1);

    // initial state (parity 0) + barrier reset
    init_state<<<192, 256>>>(inith, initc, hb, cb);

    // whole decode loop in ONE persistent kernel (128 co-resident blocks)
    decode_kernel<<<NB, 256>>>(seq_lens, labels, emb,
                               W0T, W1T, W2T,
                               bih0, bhh0, bih1, bhh1, bih2, bhh2,
                               qW0T, qb0, qW1T, qb1,
                               outW, outb, key, val,
                               hb, cb, ctx, outs);
    (void)in_sizes; (void)n_in; (void)out_size;
}

// round 17
// speedup vs baseline: 1.1027x; 1.1027x over previous
#include <cuda_runtime.h>
#include <math.h>

// Problem dims
#define HH 256
#define QQ 64
#define DD 512
#define VV 34
#define LL 1024
#define NN 64
#define TT 256
#define NB 128   // decode grid blocks (<= SM count for residency)

// ---------------- device scratch ----------------
__device__ float g_hid[65536 * 512];          // hidden of k/v MLPs (reused)
__device__ float g_key[NN * QQ * LL];         // keyT: [n][q][l]
__device__ float g_value[NN * LL * HH];       // [n][l][h]
__device__ float g_W0T[128 * 8 * 768];        // blocked [b][c][k]
__device__ float g_W1T[128 * 8 * 512];
__device__ float g_W2T[128 * 8 * 512];
__device__ float g_kW0T[512 * 512];
__device__ float g_kW1T[512 * 64];
__device__ float g_vW0T[512 * 256];
__device__ float g_vW1T[256 * 256];
__device__ float g_qW0T[256 * 256];
__device__ float g_qW1T[256 * 64];
__device__ float g_h[2 * 3 * NN * HH];        // parity-double-buffered h
__device__ float g_c[2 * 3 * NN * HH];
__device__ float g_ctx[NN * HH];

// grid barrier state (cumulative count; reset by prep each launch)
__device__ unsigned g_bcnt;
__device__ unsigned g_bgen;

__device__ __forceinline__ void gridbar(unsigned& lg)
{
    __syncthreads();
    if (threadIdx.x == 0) {
        __threadfence();
        unsigned arr = atomicAdd(&g_bcnt, 1u);
        if (arr == (unsigned)NB * (lg + 1u) - 1u) {
            atomicExch(&g_bgen, lg + 1u);
        } else {
            while (*((volatile unsigned*)&g_bgen) <= lg) __nanosleep(40);
        }
        __threadfence();
    }
    lg++;
    __syncthreads();
}

// ---------------- prep: all transposes + init state + barrier reset ----------------
// mode 0: dst[(ro+c)*KL + r] = W[r*C+c]
// mode 1 (lstm blocked): r=g*256+m -> perm=(m>>1)*8+g*2+(m&1); bb=perm>>3; cc=perm&7
//                        dst[bb*8*KL + cc*KL + (ro+c)] = W[r*C+c]
__device__ void do_tr(const float* __restrict__ W, float* __restrict__ dst,
                      int C, int ro, int mode, int KL, int bx, int by,
                      int tx, int ty)
{
    __shared__ float tile[32][33];
    int c0 = bx * 32, r0 = by * 32;
    for (int i = ty; i < 32; i += 8)
        tile[i][tx] = W[(size_t)(r0 + i) * C + c0 + tx];
    __syncthreads();
    for (int i = ty; i < 32; i += 8) {
        int c = c0 + i, r = r0 + tx;
        float v = tile[tx][i];
        if (mode == 1) {
            int m = r & 255, g = r >> 8;
            int perm = (m >> 1) * 8 + g * 2 + (m & 1);
            int bb = perm >> 3, cc = perm & 7;
            dst[(size_t)bb * 8 * KL + cc * KL + (ro + c)] = v;
        } else {
            dst[(size_t)(ro + c) * KL + r] = v;
        }
    }
}

__global__ void prep_kernel(
    const float* Wih0, const float* Whh0, const float* Wih1, const float* Whh1,
    const float* Wih2, const float* Whh2, const float* kW0, const float* kW1,
    const float* vW0, const float* vW1, const float* qW0, const float* qW1,
    const float* inith, const float* initc)
{
    int bid = blockIdx.x, t = threadIdx.x;
    int tx = t & 31, ty = t >> 5;
    if (bid == 0 && t == 0) { g_bcnt = 0u; g_bgen = 0u; }

    if (bid < 512) {            // Wih0: 1024x512, gx=16
        int lb = bid;           do_tr(Wih0, g_W0T, 512, 0, 1, 768, lb & 15, lb >> 4, tx, ty);
    } else if (bid < 768) {     // Whh0: 1024x256, gx=8
        int lb = bid - 512;     do_tr(Whh0, g_W0T, 256, 512, 1, 768, lb & 7, lb >> 3, tx, ty);
    } else if (bid < 1024) {    // Wih1
        int lb = bid - 768;     do_tr(Wih1, g_W1T, 256, 0, 1, 512, lb & 7, lb >> 3, tx, ty);
    } else if (bid < 1280) {    // Whh1
        int lb = bid - 1024;    do_tr(Whh1, g_W1T, 256, 256, 1, 512, lb & 7, lb >> 3, tx, ty);
    } else if (bid < 1536) {    // Wih2
        int lb = bid - 1280;    do_tr(Wih2, g_W2T, 256, 0, 1, 512, lb & 7, lb >> 3, tx, ty);
    } else if (bid < 1792) {    // Whh2
        int lb = bid - 1536;    do_tr(Whh2, g_W2T, 256, 256, 1, 512, lb & 7, lb >> 3, tx, ty);
    } else if (bid < 2048) {    // kW0: 512x512, gx=16
        int lb = bid - 1792;    do_tr(kW0, g_kW0T, 512, 0, 0, 512, lb & 15, lb >> 4, tx, ty);
    } else if (bid < 2080) {    // kW1: 64x512, gx=16
        int lb = bid - 2048;    do_tr(kW1, g_kW1T, 512, 0, 0, 64, lb & 15, lb >> 4, tx, ty);
    } else if (bid < 2208) {    // vW0: 256x512, gx=16
        int lb = bid - 2080;    do_tr(vW0, g_vW0T, 512, 0, 0, 256, lb & 15, lb >> 4, tx, ty);
    } else if (bid < 2272) {    // vW1: 256x256, gx=8
        int lb = bid - 2208;    do_tr(vW1, g_vW1T, 256, 0, 0, 256, lb & 7, lb >> 3, tx, ty);
    } else if (bid < 2336) {    // qW0
        int lb = bid - 2272;    do_tr(qW0, g_qW0T, 256, 0, 0, 256, lb & 7, lb >> 3, tx, ty);
    } else if (bid < 2352) {    // qW1: 64x256, gx=8
        int lb = bid - 2336;    do_tr(qW1, g_qW1T, 256, 0, 0, 64, lb & 7, lb >> 3, tx, ty);
    } else {                    // init h/c (parity 0): 192 blocks
        int idx = (bid - 2352) * 256 + t;       // 49152 total
        int i = idx >> 14, k = idx & 255;
        g_h[idx] = inith[i * 256 + k];
        g_c[idx] = initc[i * 256 + k];
    }
}

// ---------------- big GEMM: C = act(A[M,K] @ B[K,N] + bias) ----------------
// tstore: 0 linear; 1 value layout ((n<<10)+l)*N+col; 2 keyT n*65536+col*1024+l
__global__ __launch_bounds__(256) void gemm_kernel(
    const float* __restrict__ A, const float* __restrict__ B,
    const float* __restrict__ bias, float* __restrict__ C,
    int M, int N, int K, int act, int tstore)
{
    __shared__ float As[16][64];
    __shared__ float Bs[16][64];
    int t = threadIdx.x;
    int m0 = blockIdx.y << 6, n0 = blockIdx.x << 6;
    int am = t >> 2, ak = (t & 3) << 2;
    int bk = t >> 4, bn = (t & 15) << 2;
    int ty = t >> 4, tx = t & 15;
    float acc[4][4] = {};
    const float* Ap = A + (size_t)(m0 + am) * K + ak;
    const float* Bp = B + (size_t)bk * N + n0 + bn;
    for (int kc = 0; kc < K; kc += 16) {
        float4 av = *(const float4*)(Ap + kc);
        As[ak + 0][am] = av.x; As[ak + 1][am] = av.y;
        As[ak + 2][am] = av.z; As[ak + 3][am] = av.w;
        *(float4*)&Bs[bk][bn] = *(const float4*)(Bp + (size_t)kc * N);
        __syncthreads();
#pragma unroll
        for (int k = 0; k < 16; ++k) {
            float4 a4 = ((const float4*)As[k])[ty];
            float4 b4 = ((const float4*)Bs[k])[tx];
            acc[0][0] += a4.x * b4.x; acc[0][1] += a4.x * b4.y;
            acc[0][2] += a4.x * b4.z; acc[0][3] += a4.x * b4.w;
            acc[1][0] += a4.y * b4.x; acc[1][1] += a4.y * b4.y;
            acc[1][2] += a4.y * b4.z; acc[1][3] += a4.y * b4.w;
            acc[2][0] += a4.z * b4.x; acc[2][1] += a4.z * b4.y;
            acc[2][2] += a4.z * b4.z; acc[2][3] += a4.z * b4.w;
            acc[3][0] += a4.w * b4.x; acc[3][1] += a4.w * b4.y;
            acc[3][2] += a4.w * b4.z; acc[3][3] += a4.w * b4.w;
        }
        __syncthreads();
    }
#pragma unroll
    for (int i = 0; i < 4; ++i) {
        int r = m0 + ty * 4 + i;
#pragma unroll
        for (int j = 0; j < 4; ++j) {
            int col = n0 + tx * 4 + j;
            float v = acc[i][j] + bias[col];
            if (act) v = v > 0.f ? v : expm1f(v);
            size_t idx;
            if (tstore == 1) {
                int nn = r & 63, l = r >> 6;
                idx = (size_t)((nn << 10) + l) * N + col;
            } else if (tstore == 2) {
                int nn = r & 63, l = r >> 6;
                idx = ((size_t)nn << 16) + ((size_t)col << 10) + l;
            } else {
                idx = (size_t)r * N + col;
            }
            C[idx] = v;
        }
    }
}

// ---------------- decode: SMEM layout ----------------
// [0 .. 14336)          Wsm: W0 (8x768) | W1 (8x512) | W2 (8x512)   floats
// [14336 .. 19072)      union: lstm {As[2][32][64] (4096) ; gsm[64][9] (576)}
//                              attn SmAttn (2912 floats)
#define W0OFF 0
#define W1OFF 6144
#define W2OFF 10240
#define UOFF  14336
#define SMEMF 19072
#define SMEMB (SMEMF * 4)

struct SmAttn {
    float h2s[256];
    float hid[256];
    float qv[64];
    float sc[1024];
    float red[32];
    float4 part4[256];
    float ctxs[256];
};

// one LSTM layer phase. Block b owns m in {2b, 2b+1}, all 4 gates.
// Weights resident in smem (Wsm[col][K]); As double-buffered, 1 sync per chunk.
__device__ __forceinline__ void lstm_phase(
    float (*As)[32][64], float (*gsm)[9],
    const float* __restrict__ Wsm, int K, int nch,
    float bs0, float bs1,
    const float* __restrict__ r0, const float* __restrict__ r1,
    const float* __restrict__ r2,
    const float* __restrict__ cprev, float* __restrict__ cnew,
    float* __restrict__ hnew, int t, int m0)
{
    int n = t & 63, gp = t >> 6;
    int an = t >> 2, ak = (t & 3) << 2;
    const float* Wc0 = Wsm + (gp * 2) * K;
    const float* Wc1 = Wc0 + K;
    float acc0 = 0.f, acc1 = 0.f;
    const float* rows[3] = { r0, r1, r2 };

    float4 pa = *(const float4*)(r0 + ak);
    float4 pb = *(const float4*)(r0 + ak + 16);
    for (int ci = 0; ci < nch; ++ci) {
        int buf = ci & 1;
        As[buf][ak + 0][an] = pa.x;  As[buf][ak + 1][an] = pa.y;
        As[buf][ak + 2][an] = pa.z;  As[buf][ak + 3][an] = pa.w;
        As[buf][ak + 16][an] = pb.x; As[buf][ak + 17][an] = pb.y;
        As[buf][ak + 18][an] = pb.z; As[buf][ak + 19][an] = pb.w;
        __syncthreads();
        if (ci + 1 < nch) {
            int kc = (ci + 1) << 5;
            const float* src = rows[kc >> 8];
            int kk = (kc & 255) + ak;
            pa = *(const float4*)(src + kk);
            pb = *(const float4*)(src + kk + 16);
        }
        const float* wc0 = Wc0 + (ci << 5);
        const float* wc1 = Wc1 + (ci << 5);
#pragma unroll
        for (int k = 0; k < 32; k += 4) {
            float4 w0 = *(const float4*)(wc0 + k);
            float4 w1 = *(const float4*)(wc1 + k);
            float a0 = As[buf][k + 0][n], a1 = As[buf][k + 1][n];
            float a2 = As[buf][k + 2][n], a3 = As[buf][k + 3][n];
            acc0 += a0 * w0.x; acc1 += a0 * w1.x;
            acc0 += a1 * w0.y; acc1 += a1 * w1.y;
            acc0 += a2 * w0.z; acc1 += a2 * w1.z;
            acc0 += a3 * w0.w; acc1 += a3 * w1.w;
        }
    }
    gsm[n][gp * 2 + 0] = acc0 + bs0;
    gsm[n][gp * 2 + 1] = acc1 + bs1;
    __syncthreads();
    if (t < 128) {
        int nn = t >> 1, mm = t & 1;
        float i_ = gsm[nn][0 + mm];
        float f_ = gsm[nn][2 + mm];
        float g_ = gsm[nn][4 + mm];
        float o_ = gsm[nn][6 + mm];
        i_ = 1.f / (1.f + expf(-i_));
        f_ = 1.f / (1.f + expf(-f_));
        o_ = 1.f / (1.f + expf(-o_));
        int mg = m0 + mm;
        float c = f_ * cprev[nn * 256 + mg] + i_ * tanhf(g_);
        cnew[nn * 256 + mg] = c;
        hnew[nn * 256 + mg] = o_ * tanhf(c);
    }
}

// attention phase: blocks 0..63 (one per batch row). keyT layout [n][q][l].
__device__ __noinline__ void attn_phase(
    SmAttn* sp, int n, int t,
    const float* __restrict__ h2buf, const int* __restrict__ seq_lens,
    const float* __restrict__ keyT, const float* __restrict__ value,
    const float* __restrict__ qW0T, const float* __restrict__ qb0,
    const float* __restrict__ qW1T, const float* __restrict__ qb1,
    const float* __restrict__ outW, const float* __restrict__ outb,
    float* __restrict__ ctx_out, float* __restrict__ outs, int tstep)
{
    SmAttn& s = *sp;
    int w = t >> 5, lane = t & 31;
    int len = seq_lens[n];

    // q = MLP(h2)
    s.h2s[t] = h2buf[n * 256 + t];
    __syncthreads();
    {
        float a = qb0[t];
        const float* wp = qW0T + t;
#pragma unroll 16
        for (int k = 0; k < 256; ++k) a += wp[k * 256] * s.h2s[k];
        s.hid[t] = a > 0.f ? a : expm1f(a);
    }
    __syncthreads();
    if (t < 64) {
        float a = qb1[t];
        const float* wp = qW1T + t;
#pragma unroll 16
        for (int k = 0; k < 256; ++k) a += wp[k * 64] * s.hid[k];
        s.qv[t] = a;
    }
    __syncthreads();

    // scores: thread per l, coalesced over keyT rows
    {
        const float* kb = keyT + ((size_t)n << 16);
#pragma unroll
        for (int l0 = 0; l0 < 1024; l0 += 256) {
            int l = l0 + t;
            if (l < len) {
                float acc = 0.f;
                const float* kp = kb + l;
#pragma unroll
                for (int q = 0; q < 64; ++q) acc += kp[(size_t)q << 10] * s.qv[q];
                s.sc[l] = acc;
            }
        }
    }
    __syncthreads();

    // masked softmax
    float mval = -1e30f;
    for (int l = t; l < 1024; l += 256)
        if (l < len) mval = fmaxf(mval, s.sc[l]);
#pragma unroll
    for (int o = 16; o; o >>= 1) mval = fmaxf(mval, __shfl_xor_sync(0xffffffffu, mval, o));
    if (lane == 0) s.red[w] = mval;
    __syncthreads();
    if (t == 0) {
        float mm = s.red[0];
        for (int i = 1; i < 8; ++i) mm = fmaxf(mm, s.red[i]);
        s.red[8] = mm;
    }
    __syncthreads();
    float M = s.red[8];
    float sum = 0.f;
    for (int l = t; l < 1024; l += 256) {
        float e = (l < len) ? expf(s.sc[l] - M) : 0.f;
        s.sc[l] = e;
        sum += e;
    }
#pragma unroll
    for (int o = 16; o; o >>= 1) sum += __shfl_xor_sync(0xffffffffu, sum, o);
    if (lane == 0) s.red[16 + w] = sum;
    __syncthreads();
    if (t == 0) {
        float ss = 0.f;
        for (int i = 0; i < 8; ++i) ss += s.red[16 + i];
        s.red[9] = 1.f / ss;
    }
    __syncthreads();
    float inv = s.red[9];

    // ctx = a @ value   (value layout [n][l][h]) — deep unroll for MLP
    {
        int hv = t & 63, lc = t >> 6;
        int l0 = lc << 8;
        int l1 = min(l0 + 256, len);
        float4 a4 = make_float4(0.f, 0.f, 0.f, 0.f);
        const float* vb = value + ((size_t)(n << 10)) * 256 + (hv << 2);
#pragma unroll 8
        for (int l = l0; l < l1; ++l) {
            float a = s.sc[l];
            float4 v4 = *(const float4*)(vb + ((size_t)l << 8));
            a4.x += a * v4.x; a4.y += a * v4.y;
            a4.z += a * v4.z; a4.w += a * v4.w;
        }
        s.part4[t] = a4;
    }
    __syncthreads();
    if (t < 64) {
        float4 r = s.part4[t], b1 = s.part4[t + 64], b2 = s.part4[t + 128], b3 = s.part4[t + 192];
        r.x = (r.x + b1.x + b2.x + b3.x) * inv;
        r.y = (r.y + b1.y + b2.y + b3.y) * inv;
        r.z = (r.z + b1.z + b2.z + b3.z) * inv;
        r.w = (r.w + b1.w + b2.w + b3.w) * inv;
        s.ctxs[t * 4 + 0] = r.x; s.ctxs[t * 4 + 1] = r.y;
        s.ctxs[t * 4 + 2] = r.z; s.ctxs[t * 4 + 3] = r.w;
        *(float4*)(ctx_out + n * 256 + t * 4) = r;
    }
    __syncthreads();

    // out = [ctx, h2] @ outW^T + outb
    if (tstep >= 0) {
        for (int v = w; v < 34; v += 8) {
            const float* wr = outW + v * 512;
            float a = 0.f;
#pragma unroll
            for (int kk = 0; kk < 16; ++kk) {
                int k = kk * 32 + lane;
                float x = (k < 256) ? s.ctxs[k] : s.h2s[k - 256];
                a += x * wr[k];
            }
#pragma unroll
            for (int o = 16; o; o >>= 1) a += __shfl_xor_sync(0xffffffffu, a, o);
            if (lane == 0)
                outs[((size_t)tstep * 64 + n) * 34 + v] = a + outb[v];
        }
    }
}

__global__ __launch_bounds__(256) void decode_kernel(
    const int* __restrict__ seq_lens, const int* __restrict__ labels,
    const float* __restrict__ emb,
    const float* __restrict__ W0T, const float* __restrict__ W1T,
    const float* __restrict__ W2T,
    const float* __restrict__ bih0, const float* __restrict__ bhh0,
    const float* __restrict__ bih1, const float* __restrict__ bhh1,
    const float* __restrict__ bih2, const float* __restrict__ bhh2,
    const float* __restrict__ qW0T, const float* __restrict__ qb0,
    const float* __restrict__ qW1T, const float* __restrict__ qb1,
    const float* __restrict__ outW, const float* __restrict__ outb,
    const float* __restrict__ keyT, const float* __restrict__ value,
    float* __restrict__ hb, float* __restrict__ cb,
    float* __restrict__ ctx, float* __restrict__ outs)
{
    extern __shared__ float smp[];
    float* Wsm0 = smp + W0OFF;
    float* Wsm1 = smp + W1OFF;
    float* Wsm2 = smp + W2OFF;
    float (*As)[32][64] = (float(*)[32][64])(smp + UOFF);
    float (*gsm)[9] = (float(*)[9])(smp + UOFF + 4096);
    SmAttn* sa = (SmAttn*)(smp + UOFF);

    unsigned lg = 0;
    int b = blockIdx.x, t = threadIdx.x;
    const int NS = NN * HH;   // 16384
    int m0 = b << 1;
    int gp = t >> 6;
    int c0 = gp * 256 + m0, c1 = c0 + 1;

    // preload this block's weight slices (once)
    {
        const float* w0g = W0T + (size_t)b * 8 * 768;
        const float* w1g = W1T + (size_t)b * 8 * 512;
        const float* w2g = W2T + (size_t)b * 8 * 512;
        for (int i = t * 4; i < 6144; i += 1024)
            *(float4*)(Wsm0 + i) = *(const float4*)(w0g + i);
        for (int i = t * 4; i < 4096; i += 1024) {
            *(float4*)(Wsm1 + i) = *(const float4*)(w1g + i);
            *(float4*)(Wsm2 + i) = *(const float4*)(w2g + i);
        }
    }
    // hoist per-thread bias sums
    float b00 = bih0[c0] + bhh0[c0], b01 = bih0[c1] + bhh0[c1];
    float b10 = bih1[c0] + bhh1[c0], b11 = bih1[c1] + bhh1[c1];
    float b20 = bih2[c0] + bhh2[c0], b21 = bih2[c1] + bhh2[c1];
    int an = t >> 2;
    __syncthreads();

    // initial ctx from h_init (parity 0)
    if (b < 64)
        attn_phase(sa, b, t, hb + 2 * NS, seq_lens, keyT, value,
                   qW0T, qb0, qW1T, qb1, outW, outb, ctx, outs, -1);
    gridbar(lg);

    for (int st = 0; st < TT; ++st) {
        int p = st & 1, q = p ^ 1;
        float* hp = hb + (size_t)p * 3 * NS;
        float* hq = hb + (size_t)q * 3 * NS;
        float* cp = cb + (size_t)p * 3 * NS;
        float* cq = cb + (size_t)q * 3 * NS;
        int lv = labels[st * 64 + an];

        lstm_phase(As, gsm, Wsm0, 768, 24, b00, b01,
                   ctx + an * 256, emb + lv * 256, hp + 0 * NS + an * 256,
                   cp + 0 * NS, cq + 0 * NS, hq + 0 * NS, t, m0);
        gridbar(lg);
        lstm_phase(As, gsm, Wsm1, 512, 16, b10, b11,
                   hq + 0 * NS + an * 256, hp + 1 * NS + an * 256, (const float*)0,
                   cp + 1 * NS, cq + 1 * NS, hq + 1 * NS, t, m0);
        gridbar(lg);
        lstm_phase(As, gsm, Wsm2, 512, 16, b20, b21,
                   hq + 1 * NS + an * 256, hp + 2 * NS + an * 256, (const float*)0,
                   cp + 2 * NS, cq + 2 * NS, hq + 2 * NS, t, m0);
        gridbar(lg);
        if (b < 64)
            attn_phase(sa, b, t, hq + 2 * NS, seq_lens, keyT, value,
                       qW0T, qb0, qW1T, qb1, outW, outb, ctx, outs, st);
        gridbar(lg);
    }
}

// ---------------- host ----------------
extern "C" void kernel_launch(void* const* d_in, const int* in_sizes, int n_in,
                              void* d_out, int out_size)
{
    const float* seqs     = (const float*)d_in[0];
    const int*   seq_lens = (const int*)  d_in[1];
    const int*   labels   = (const int*)  d_in[2];
    const float* emb      = (const float*)d_in[3];
    const float* inith    = (const float*)d_in[4];
    const float* initc    = (const float*)d_in[5];
    const float* Wih0 = (const float*)d_in[6],  *Whh0 = (const float*)d_in[7];
    const float* bih0 = (const float*)d_in[8],  *bhh0 = (const float*)d_in[9];
    const float* Wih1 = (const float*)d_in[10], *Whh1 = (const float*)d_in[11];
    const float* bih1 = (const float*)d_in[12], *bhh1 = (const float*)d_in[13];
    const float* Wih2 = (const float*)d_in[14], *Whh2 = (const float*)d_in[15];
    const float* bih2 = (const float*)d_in[16], *bhh2 = (const float*)d_in[17];
    const float* qW0 = (const float*)d_in[18], *qb0 = (const float*)d_in[19];
    const float* qW1 = (const float*)d_in[20], *qb1 = (const float*)d_in[21];
    const float* kW0 = (const float*)d_in[22], *kb0 = (const float*)d_in[23];
    const float* kW1 = (const float*)d_in[24], *kb1 = (const float*)d_in[25];
    const float* vW0 = (const float*)d_in[26], *vb0 = (const float*)d_in[27];
    const float* vW1 = (const float*)d_in[28], *vb1 = (const float*)d_in[29];
    const float* outW = (const float*)d_in[30], *outb = (const float*)d_in[31];
    float* outs = (float*)d_out;

    float *hid, *key, *val, *W0T, *W1T, *W2T;
    float *kW0T, *kW1T, *vW0T, *vW1T, *qW0T, *qW1T;
    float *hb, *cb, *ctx;
    cudaGetSymbolAddress((void**)&hid,  g_hid);
    cudaGetSymbolAddress((void**)&key,  g_key);
    cudaGetSymbolAddress((void**)&val,  g_value);
    cudaGetSymbolAddress((void**)&W0T,  g_W0T);
    cudaGetSymbolAddress((void**)&W1T,  g_W1T);
    cudaGetSymbolAddress((void**)&W2T,  g_W2T);
    cudaGetSymbolAddress((void**)&kW0T, g_kW0T);
    cudaGetSymbolAddress((void**)&kW1T, g_kW1T);
    cudaGetSymbolAddress((void**)&vW0T, g_vW0T);
    cudaGetSymbolAddress((void**)&vW1T, g_vW1T);
    cudaGetSymbolAddress((void**)&qW0T, g_qW0T);
    cudaGetSymbolAddress((void**)&qW1T, g_qW1T);
    cudaGetSymbolAddress((void**)&hb,   g_h);
    cudaGetSymbolAddress((void**)&cb,   g_c);
    cudaGetSymbolAddress((void**)&ctx,  g_ctx);

    cudaFuncSetAttribute(decode_kernel,
                         cudaFuncAttributeMaxDynamicSharedMemorySize, SMEMB);

    // 1) prep: all transposes (lstm weights into blocked layout) + init + barrier reset
    prep_kernel<<<2544, 256>>>(Wih0, Whh0, Wih1, Whh1, Wih2, Whh2,
                               kW0, kW1, vW0, vW1, qW0, qW1, inith, initc);

    // 2-5) key / value precompute (key stored transposed [n][q][l])
    gemm_kernel<<<dim3(8, 1024), 256>>>(seqs, kW0T, kb0, hid, 65536, 512, 512, 1, 0);
    gemm_kernel<<<dim3(1, 1024), 256>>>(hid, kW1T, kb1, key, 65536, 64, 512, 0, 2);
    gemm_kernel<<<dim3(4, 1024), 256>>>(seqs, vW0T, vb0, hid, 65536, 256, 512, 1, 0);
    gemm_kernel<<<dim3(4, 1024), 256>>>(hid, vW1T, vb1, val, 65536, 256, 256, 0, 1);

    // 6) whole decode loop in ONE persistent kernel (launch index 5 -> ncu target)
    decode_kernel<<<NB, 256, SMEMB>>>(seq_lens, labels, emb,
                                      W0T, W1T, W2T,
                                      bih0, bhh0, bih1, bhh1, bih2, bhh2,
                                      qW0T, qb0, qW1T, qb1,
                                      outW, outb, key, val,
                                      hb, cb, ctx, outs);
    (void)in_sizes; (void)n_in; (void)out_size;
}